// round 5
// baseline (speedup 1.0000x reference)
#include <cuda_runtime.h>
#include <cuda_bf16.h>
#include <math.h>

// ---------------------------------------------------------------------------
// MegatronAttention B=2,S=2048,H=2048,NH=16,DH=128 — mma.sync bf16x3-split GEMMs
// CTA tile 128x256, warp tile 64x64, KC=64, 2-stage cp.async pipeline.
// out quirk: einsum 'bhqk,bhkd->bhkd' sums q -> out = v * colsum(softmax).
// ---------------------------------------------------------------------------
#define SEQ 2048
#define HDIM 2048
#define NH 16
#define DHEAD 128
#define MR 4096               // B*S
#define QN 6144               // 3*NH*DH
#define NBH 32
#define NTILES 32             // 2048/64 score col-tiles per row

typedef long long ll;
typedef unsigned int u32;

// --------------------------- scratch buffers -------------------------------
__device__ __nv_bfloat16 g_xhi[(size_t)MR*HDIM], g_xlo[(size_t)MR*HDIM];
__device__ __nv_bfloat16 g_wqT_hi[(size_t)QN*HDIM], g_wqT_lo[(size_t)QN*HDIM];
__device__ __nv_bfloat16 g_woT_hi[(size_t)HDIM*HDIM], g_woT_lo[(size_t)HDIM*HDIM];
__device__ __nv_bfloat16 g_qkv_hi[(size_t)MR*QN], g_qkv_lo[(size_t)MR*QN];
__device__ float g_scores[(size_t)NBH*SEQ*SEQ];
__device__ __nv_bfloat16 g_vhi[(size_t)MR*HDIM], g_vlo[(size_t)MR*HDIM];
__device__ float g_pmax[(size_t)NBH*SEQ*NTILES], g_psum[(size_t)NBH*SEQ*NTILES];
__device__ float g_rowmax[NBH*SEQ], g_rowinv[NBH*SEQ], g_colsum[NBH*SEQ];

// --------------------------- helpers ---------------------------------------
__device__ __forceinline__ u32 s2u(const void* p){
    u32 a; asm("{ .reg .u64 t; cvta.to.shared.u64 t, %1; cvt.u32.u64 %0, t; }":"=r"(a):"l"(p)); return a;
}
#define SWZ(o) ((o) ^ (((o)>>3)&0x70))

__device__ __forceinline__ void cpa16(u32 d, const void* s){
    asm volatile("cp.async.cg.shared.global [%0], [%1], 16;" :: "r"(d), "l"(s));
}
__device__ __forceinline__ void cpc(){ asm volatile("cp.async.commit_group;"); }
template<int N> __device__ __forceinline__ void cpw(){ asm volatile("cp.async.wait_group %0;"::"n"(N)); }

__device__ __forceinline__ void ldm4(u32* r, u32 addr){
    asm volatile("ldmatrix.sync.aligned.m8n8.x4.shared.b16 {%0,%1,%2,%3}, [%4];"
        : "=r"(r[0]),"=r"(r[1]),"=r"(r[2]),"=r"(r[3]) : "r"(addr));
}
__device__ __forceinline__ void mma16816(float* d, const u32* a, u32 b0, u32 b1){
    asm volatile("mma.sync.aligned.m16n8k16.row.col.f32.bf16.bf16.f32 "
        "{%0,%1,%2,%3}, {%4,%5,%6,%7}, {%8,%9}, {%0,%1,%2,%3};"
        : "+f"(d[0]),"+f"(d[1]),"+f"(d[2]),"+f"(d[3])
        : "r"(a[0]),"r"(a[1]),"r"(a[2]),"r"(a[3]), "r"(b0),"r"(b1));
}
__device__ __forceinline__ void bsplit(float v, __nv_bfloat16& h, __nv_bfloat16& l){
    h = __float2bfloat16(v);
    l = __float2bfloat16(v - __bfloat162float(h));
}

// --------------------------- mma.sync GEMM ---------------------------------
// C[M,N] = alpha * sum_k A[m,k]*B[n,k] (row-major, k contiguous; "NT").
// A/B pre-split bf16 hi/lo; 3-term product.
#define KC 64
#define A_TILE 16384              // 128 x 128B
#define B_TILE 32768              // 256 x 128B
#define STAGE_BYTES (2*A_TILE + 2*B_TILE)   // 96KB
#define GSMEM_SZ (1024 + 2*STAGE_BYTES)

// EPI: 0 = f32 out, 1 = split bf16 hi/lo out, 2 = f32 scores + partial softmax
template<int EPI>
__global__ __launch_bounds__(256, 1)
void gemm_mma(const __nv_bfloat16* __restrict__ Ahi, const __nv_bfloat16* __restrict__ Alo,
              const __nv_bfloat16* __restrict__ Bhi, const __nv_bfloat16* __restrict__ Blo,
              float* __restrict__ Cf, __nv_bfloat16* __restrict__ Chi, __nv_bfloat16* __restrict__ Clo,
              float* __restrict__ Pm, float* __restrict__ Ps,
              int K, int lda, int ldb, int ldc, int zdiv,
              ll sAo, ll sAi, ll sBo, ll sBi, ll sCo, ll sCi, float alpha)
{
    extern __shared__ char smem[];
    const u32 stage0 = (s2u(smem) + 1023u) & ~1023u;
    const int tid = threadIdx.x;
    const int lane = tid & 31;
    const int wid = tid >> 5;
    const int wm = (wid & 1) * 64;          // warp M offset (2 rows of warps)
    const int wn = (wid >> 1) * 64;         // warp N offset (4 cols of warps)
    const int lrow16 = lane & 15;
    const int lcol16 = (lane >> 4) * 16;

    const int zo = blockIdx.z / zdiv, zi = blockIdx.z % zdiv;
    Ahi += zo*sAo + zi*sAi;  Alo += zo*sAo + zi*sAi;
    Bhi += zo*sBo + zi*sBi;  Blo += zo*sBo + zi*sBi;
    const ll coff = zo*sCo + zi*sCi;

    const int m0 = blockIdx.y * 128;
    const int n0 = blockIdx.x * 256;
    const int NK = K / KC;

    // loader mapping: A tiles 128 rows x 8 segs (2 thr/row, 4 segs each);
    //                 B tiles 256 rows x 8 segs (1 thr/row, 8 segs each)
    const int arow = tid >> 1;
    const int aseg0 = (tid & 1) * 4;

    auto fetch_stage = [&](int s){
        const u32 base = stage0 + (s & 1) * STAGE_BYTES;
        const int k0 = s * KC;
        // A hi/lo
        #pragma unroll
        for (int t = 0; t < 2; t++) {
            const __nv_bfloat16* gp = (t ? Alo : Ahi) + (ll)(m0 + arow)*lda + k0 + aseg0*8;
            const u32 dbase = base + t * A_TILE;
            #pragma unroll
            for (int j = 0; j < 4; j++)
                cpa16(dbase + SWZ((u32)(arow*128 + (aseg0 + j)*16)), gp + j*8);
        }
        // B hi/lo
        #pragma unroll
        for (int t = 0; t < 2; t++) {
            const __nv_bfloat16* gp = (t ? Blo : Bhi) + (ll)(n0 + tid)*ldb + k0;
            const u32 dbase = base + 2*A_TILE + t * B_TILE;
            #pragma unroll
            for (int j = 0; j < 8; j++)
                cpa16(dbase + SWZ((u32)(tid*128 + j*16)), gp + j*8);
        }
        cpc();
    };

    float acc[4][8][4];
    #pragma unroll
    for (int i=0;i<4;i++)
    #pragma unroll
    for (int j=0;j<8;j++)
    #pragma unroll
    for (int r=0;r<4;r++) acc[i][j][r] = 0.f;

    fetch_stage(0);
    for (int kc = 0; kc < NK; kc++) {
        if (kc + 1 < NK) { fetch_stage(kc+1); cpw<1>(); } else { cpw<0>(); }
        __syncthreads();

        const u32 sb  = stage0 + (kc & 1) * STAGE_BYTES;
        const u32 sAh = sb, sAl = sb + A_TILE;
        const u32 sBh = sb + 2*A_TILE, sBl = sb + 2*A_TILE + B_TILE;

        #pragma unroll
        for (int k16 = 0; k16 < 4; k16++) {
            u32 ah[4][4], al[4][4];
            #pragma unroll
            for (int mf = 0; mf < 4; mf++) {
                u32 off = SWZ((u32)((wm + mf*16 + lrow16)*128 + k16*32 + lcol16));
                ldm4(ah[mf], sAh + off);
                ldm4(al[mf], sAl + off);
            }
            #pragma unroll
            for (int n2 = 0; n2 < 4; n2++) {
                u32 bh[4], bl[4];
                u32 off = SWZ((u32)((wn + n2*16 + lrow16)*128 + k16*32 + lcol16));
                ldm4(bh, sBh + off);
                ldm4(bl, sBl + off);
                #pragma unroll
                for (int od = 0; od < 2; od++) {
                    const int nf = n2*2 + od;
                    #pragma unroll
                    for (int mf = 0; mf < 4; mf++) {
                        mma16816(acc[mf][nf], ah[mf], bh[od], bh[od+2]);
                        mma16816(acc[mf][nf], ah[mf], bl[od], bl[od+2]);
                        mma16816(acc[mf][nf], al[mf], bh[od], bh[od+2]);
                    }
                }
            }
        }
        __syncthreads();
    }

    // scale by alpha
    #pragma unroll
    for (int i=0;i<4;i++)
    #pragma unroll
    for (int j=0;j<8;j++)
    #pragma unroll
    for (int r=0;r<4;r++) acc[i][j][r] *= alpha;

    const int g = lane >> 2, tig = lane & 3;
    // stores
    #pragma unroll
    for (int mf = 0; mf < 4; mf++) {
        #pragma unroll
        for (int nf = 0; nf < 8; nf++) {
            const ll m = m0 + wm + mf*16 + g;
            const int n = n0 + wn + nf*8 + tig*2;
            float d0 = acc[mf][nf][0], d1 = acc[mf][nf][1];
            float d2 = acc[mf][nf][2], d3 = acc[mf][nf][3];
            if (EPI != 1) {
                float2 v01 = {d0, d1}, v23 = {d2, d3};
                *reinterpret_cast<float2*>(Cf + coff + m*ldc + n) = v01;
                *reinterpret_cast<float2*>(Cf + coff + (m+8)*ldc + n) = v23;
            } else {
                __nv_bfloat16 h0,l0,h1,l1,h2,l2,h3,l3;
                bsplit(d0,h0,l0); bsplit(d1,h1,l1); bsplit(d2,h2,l2); bsplit(d3,h3,l3);
                __nv_bfloat162 hh01; hh01.x=h0; hh01.y=h1;
                __nv_bfloat162 ll01; ll01.x=l0; ll01.y=l1;
                __nv_bfloat162 hh23; hh23.x=h2; hh23.y=h3;
                __nv_bfloat162 ll23; ll23.x=l2; ll23.y=l3;
                *reinterpret_cast<u32*>(Chi + coff + m*ldc + n) = *reinterpret_cast<u32*>(&hh01);
                *reinterpret_cast<u32*>(Clo + coff + m*ldc + n) = *reinterpret_cast<u32*>(&ll01);
                *reinterpret_cast<u32*>(Chi + coff + (m+8)*ldc + n) = *reinterpret_cast<u32*>(&hh23);
                *reinterpret_cast<u32*>(Clo + coff + (m+8)*ldc + n) = *reinterpret_cast<u32*>(&ll23);
            }
        }
    }

    if (EPI == 2) {
        // partial softmax stats: per row, over this warp's 64 cols
        const int bh = blockIdx.z;
        const int nt = (n0 + wn) >> 6;       // 0..31
        #pragma unroll
        for (int mf = 0; mf < 4; mf++) {
            #pragma unroll
            for (int half = 0; half < 2; half++) {
                const int r0i = half * 2;    // regs 0,1 or 2,3
                float mx = -1e30f;
                #pragma unroll
                for (int nf = 0; nf < 8; nf++)
                    mx = fmaxf(mx, fmaxf(acc[mf][nf][r0i], acc[mf][nf][r0i+1]));
                mx = fmaxf(mx, __shfl_xor_sync(0xffffffffu, mx, 1));
                mx = fmaxf(mx, __shfl_xor_sync(0xffffffffu, mx, 2));
                float sm = 0.f;
                #pragma unroll
                for (int nf = 0; nf < 8; nf++)
                    sm += __expf(acc[mf][nf][r0i] - mx) + __expf(acc[mf][nf][r0i+1] - mx);
                sm += __shfl_xor_sync(0xffffffffu, sm, 1);
                sm += __shfl_xor_sync(0xffffffffu, sm, 2);
                if (tig == 0) {
                    const int row = m0 + wm + mf*16 + g + half*8;
                    const ll idx = ((ll)bh*SEQ + row)*NTILES + nt;
                    Pm[idx] = mx; Ps[idx] = sm;
                }
            }
        }
    }
}

// --------------------------- prep kernels ----------------------------------
__global__ __launch_bounds__(256)
void split_x_kernel(const float* __restrict__ x, __nv_bfloat16* __restrict__ hi,
                    __nv_bfloat16* __restrict__ lo)
{
    const ll i = (ll)blockIdx.x * 256 + threadIdx.x;
    float v = x[i];
    __nv_bfloat16 h, l; bsplit(v, h, l);
    hi[i] = h; lo[i] = l;
}

// in [R,C] f32 -> out [C,R] split bf16
__global__ __launch_bounds__(256)
void transpose_split_kernel(const float* __restrict__ in, __nv_bfloat16* __restrict__ ohi,
                            __nv_bfloat16* __restrict__ olo, int R, int C)
{
    __shared__ float t[32][33];
    const int c0 = blockIdx.x * 32, r0 = blockIdx.y * 32;
    const int tx = threadIdx.x, ty = threadIdx.y;
    #pragma unroll
    for (int i = 0; i < 4; i++)
        t[ty + 8*i][tx] = in[(ll)(r0 + ty + 8*i) * C + c0 + tx];
    __syncthreads();
    #pragma unroll
    for (int i = 0; i < 4; i++) {
        float v = t[tx][ty + 8*i];
        __nv_bfloat16 h, l; bsplit(v, h, l);
        const ll o = (ll)(c0 + ty + 8*i) * R + r0 + tx;
        ohi[o] = h; olo[o] = l;
    }
}

// --------------------------- stats combine ---------------------------------
// one warp per row: combine 32 (pmax, psum) partials -> rowmax, rowinv
__global__ __launch_bounds__(256)
void stats_combine_kernel(const float* __restrict__ Pm, const float* __restrict__ Ps,
                          float* __restrict__ rowmax, float* __restrict__ rowinv)
{
    const int row = blockIdx.x * 8 + (threadIdx.x >> 5);
    const int lane = threadIdx.x & 31;
    float m = Pm[(ll)row*NTILES + lane];
    float s = Ps[(ll)row*NTILES + lane];
    float gm = m;
    #pragma unroll
    for (int o = 16; o; o >>= 1) gm = fmaxf(gm, __shfl_xor_sync(0xffffffffu, gm, o));
    float z = s * __expf(m - gm);
    #pragma unroll
    for (int o = 16; o; o >>= 1) z += __shfl_xor_sync(0xffffffffu, z, o);
    if (lane == 0) { rowmax[row] = gm; rowinv[row] = 1.0f / z; }
}

// colsum with q-split + atomics: grid (k_chunks, bh, q_chunks)
__global__ __launch_bounds__(256)
void colsum2_kernel(const float* __restrict__ S, const float* __restrict__ rowmax,
                    const float* __restrict__ rowinv, float* __restrict__ colsum)
{
    const int bh = blockIdx.y;
    const int k  = blockIdx.x * 256 + threadIdx.x;
    const int q0 = blockIdx.z * 128;
    const float* sp = S + (ll)bh*SEQ*SEQ + (ll)q0*SEQ + k;
    const float* mp = rowmax + bh*SEQ + q0;
    const float* ip = rowinv + bh*SEQ + q0;
    float acc = 0.f;
    #pragma unroll 4
    for (int q = 0; q < 128; q++)
        acc += __expf(sp[(ll)q*SEQ] - __ldg(&mp[q])) * __ldg(&ip[q]);
    atomicAdd(&colsum[bh*SEQ + k], acc);
}

// vals = v * colsum, re-split to bf16 hi/lo
__global__ __launch_bounds__(256)
void scale_v_split_kernel(const __nv_bfloat16* __restrict__ qhi, const __nv_bfloat16* __restrict__ qlo,
                          const float* __restrict__ colsum,
                          __nv_bfloat16* __restrict__ vhi, __nv_bfloat16* __restrict__ vlo)
{
    const ll idx = (ll)blockIdx.x * 256 + threadIdx.x;
    const int col = (int)(idx & (HDIM - 1));
    const int row = (int)(idx >> 11);
    const int h = col >> 7;
    const int b = row >> 11;
    const int s = row & (SEQ - 1);
    const ll qo = (ll)row * QN + 2*NH*DHEAD + col;
    float v = __bfloat162float(qhi[qo]) + __bfloat162float(qlo[qo]);
    v *= colsum[(b*NH + h)*SEQ + s];
    __nv_bfloat16 h16, l16; bsplit(v, h16, l16);
    vhi[idx] = h16; vlo[idx] = l16;
}

// ---------------------------------------------------------------------------
extern "C" void kernel_launch(void* const* d_in, const int* in_sizes, int n_in,
                              void* d_out, int out_size)
{
    const float* x     = (const float*)d_in[0];
    const float* w_qkv = (const float*)d_in[1];
    const float* w_o   = (const float*)d_in[2];
    float* out = (float*)d_out;

    __nv_bfloat16 *xhi,*xlo,*wqh,*wql,*woh,*wol,*qh,*qlp,*vh,*vl;
    float *scores,*rowmax,*rowinv,*colsum,*pmax,*psum;
    cudaGetSymbolAddress((void**)&xhi, g_xhi);   cudaGetSymbolAddress((void**)&xlo, g_xlo);
    cudaGetSymbolAddress((void**)&wqh, g_wqT_hi); cudaGetSymbolAddress((void**)&wql, g_wqT_lo);
    cudaGetSymbolAddress((void**)&woh, g_woT_hi); cudaGetSymbolAddress((void**)&wol, g_woT_lo);
    cudaGetSymbolAddress((void**)&qh,  g_qkv_hi); cudaGetSymbolAddress((void**)&qlp, g_qkv_lo);
    cudaGetSymbolAddress((void**)&vh,  g_vhi);    cudaGetSymbolAddress((void**)&vl,  g_vlo);
    cudaGetSymbolAddress((void**)&scores, g_scores);
    cudaGetSymbolAddress((void**)&rowmax, g_rowmax);
    cudaGetSymbolAddress((void**)&rowinv, g_rowinv);
    cudaGetSymbolAddress((void**)&colsum, g_colsum);
    cudaGetSymbolAddress((void**)&pmax, g_pmax);
    cudaGetSymbolAddress((void**)&psum, g_psum);

    cudaFuncSetAttribute(gemm_mma<0>, cudaFuncAttributeMaxDynamicSharedMemorySize, GSMEM_SZ);
    cudaFuncSetAttribute(gemm_mma<1>, cudaFuncAttributeMaxDynamicSharedMemorySize, GSMEM_SZ);
    cudaFuncSetAttribute(gemm_mma<2>, cudaFuncAttributeMaxDynamicSharedMemorySize, GSMEM_SZ);

    // prep: split/transpose inputs
    split_x_kernel<<<(MR*HDIM)/256, 256>>>(x, xhi, xlo);
    transpose_split_kernel<<<dim3(QN/32, HDIM/32), dim3(32,8)>>>(w_qkv, wqh, wql, HDIM, QN);
    transpose_split_kernel<<<dim3(HDIM/32, HDIM/32), dim3(32,8)>>>(w_o, woh, wol, HDIM, HDIM);

    // 1) qkv = x @ w_qkv  (split bf16 out)
    gemm_mma<1><<<dim3(QN/256, MR/128, 1), 256, GSMEM_SZ>>>(
        xhi, xlo, wqh, wql, nullptr, qh, qlp, nullptr, nullptr,
        HDIM, HDIM, HDIM, QN, 1, 0,0,0,0,0,0, 1.0f);

    // 2) scores = (Q @ K^T)/sqrt(128) + partial softmax stats, z = b*16+h
    gemm_mma<2><<<dim3(SEQ/256, SEQ/128, NBH), 256, GSMEM_SZ>>>(
        qh, qlp, qh + NH*DHEAD, qlp + NH*DHEAD, scores, nullptr, nullptr, pmax, psum,
        DHEAD, QN, QN, SEQ, NH,
        (ll)SEQ*QN, 128, (ll)SEQ*QN, 128,
        (ll)NH*SEQ*SEQ, (ll)SEQ*SEQ, 0.08838834764831845f);

    // 3) combine partial stats
    stats_combine_kernel<<<(NBH*SEQ)/8, 256>>>(pmax, psum, rowmax, rowinv);

    // 4) colsum over q (atomic, q-split)
    cudaMemsetAsync(colsum, 0, NBH*SEQ*sizeof(float));
    colsum2_kernel<<<dim3(SEQ/256, NBH, SEQ/128), 256>>>(scores, rowmax, rowinv, colsum);

    // 5) vals = v * colsum, split
    scale_v_split_kernel<<<(MR*HDIM)/256, 256>>>(qh, qlp, colsum, vh, vl);

    // 6) out = vals @ w_o
    gemm_mma<0><<<dim3(HDIM/256, MR/128, 1), 256, GSMEM_SZ>>>(
        vh, vl, woh, wol, out, nullptr, nullptr, nullptr, nullptr,
        HDIM, HDIM, HDIM, HDIM, 1, 0,0,0,0,0,0, 1.0f);
}